// round 1
// baseline (speedup 1.0000x reference)
#include <cuda_runtime.h>
#include <cuda_bf16.h>
#include <math.h>

// ---------------- Problem constants ----------------
#define BB 2
#define SS 1024
#define DD 768
#define HH 12
#define HD 64
#define LL 4
#define VV 50257
#define BSr (BB*SS)          // 2048 rows
#define D3 (3*DD)            // 2304
#define D4 (4*DD)            // 3072
#define BH (BB*HH)           // 24

// ---------------- Scratch (device globals, no allocation) ----------------
__device__ float g_h[BSr*DD];
__device__ float g_xln[BSr*DD];
__device__ float g_qkv[BSr*D3];
__device__ float g_scores[(size_t)BH*SS*SS];   // 100 MB
__device__ float g_abuf[BSr*DD];
__device__ float g_fc[BSr*D4];

// ---------------- Helpers ----------------
__device__ __forceinline__ float gelu_f(float x) {
    const float c = 0.7978845608028654f;
    float t = tanhf(c * (x + 0.044715f * x * x * x));
    return 0.5f * x * (1.0f + t);
}

// ---------------- Embedding: h = wte[X] + wpe[s] ----------------
__global__ void embed_kernel(const int* __restrict__ X, const float* __restrict__ wte,
                             const float* __restrict__ wpe, float* __restrict__ h) {
    int bs = blockIdx.x;              // 0..2047
    int s = bs & (SS - 1);
    int tok = X[bs];
    const float* we = wte + (size_t)tok * DD;
    const float* wp = wpe + (size_t)s * DD;
    float* out = h + (size_t)bs * DD;
    int tid = threadIdx.x;
#pragma unroll
    for (int q = 0; q < 3; q++) {
        int d = tid + q * 256;
        out[d] = we[d] + wp[d];
    }
}

// ---------------- LayerNorm (row = block, 768 = 3*256) ----------------
__global__ void layernorm_kernel(const float* __restrict__ in, const float* __restrict__ g,
                                 const float* __restrict__ b, float* __restrict__ out) {
    int r = blockIdx.x;
    int tid = threadIdx.x;
    const float* x = in + (size_t)r * DD;
    float v0 = x[tid], v1 = x[tid + 256], v2 = x[tid + 512];
    __shared__ float red[256];
    red[tid] = v0 + v1 + v2;
    __syncthreads();
    for (int s = 128; s > 0; s >>= 1) { if (tid < s) red[tid] += red[tid + s]; __syncthreads(); }
    float m = red[0] * (1.0f / DD);
    __syncthreads();
    float d0 = v0 - m, d1 = v1 - m, d2 = v2 - m;
    red[tid] = d0 * d0 + d1 * d1 + d2 * d2;
    __syncthreads();
    for (int s = 128; s > 0; s >>= 1) { if (tid < s) red[tid] += red[tid + s]; __syncthreads(); }
    float inv = rsqrtf(red[0] * (1.0f / DD) + 1e-5f);
    float* o = out + (size_t)r * DD;
    o[tid]       = d0 * inv * g[tid]       + b[tid];
    o[tid + 256] = d1 * inv * g[tid + 256] + b[tid + 256];
    o[tid + 512] = d2 * inv * g[tid + 512] + b[tid + 512];
}

// ---------------- SGEMM NN: C[M,N] = A[M,K] @ B[K,N] + bias (+epilogue) ----------------
// 128x128 tile, BK=8, 256 threads, 8x8 per thread. M%128==0, N%128==0, K%8==0.
// EPI: 0=bias, 1=bias+gelu, 2=bias+residual add (res is [M,N], same N)
template <int EPI>
__global__ void sgemm_nn(const float* __restrict__ A, const float* __restrict__ B,
                         const float* __restrict__ bias, const float* __restrict__ res,
                         float* __restrict__ C, int M, int N, int K) {
    __shared__ float As[8][128];
    __shared__ float Bs[8][128];
    int tid = threadIdx.x;
    int row0 = blockIdx.y * 128, col0 = blockIdx.x * 128;
    int tx = tid & 15, ty = tid >> 4;
    int a_row = tid >> 1, a_k4 = (tid & 1) * 4;
    int b_k = tid >> 5, b_n4 = (tid & 31) * 4;
    float acc[8][8];
#pragma unroll
    for (int i = 0; i < 8; i++)
#pragma unroll
        for (int j = 0; j < 8; j++) acc[i][j] = 0.0f;

    for (int k0 = 0; k0 < K; k0 += 8) {
        float4 av = *(const float4*)(A + (size_t)(row0 + a_row) * K + k0 + a_k4);
        float4 bv = *(const float4*)(B + (size_t)(k0 + b_k) * N + col0 + b_n4);
        As[a_k4 + 0][a_row] = av.x;
        As[a_k4 + 1][a_row] = av.y;
        As[a_k4 + 2][a_row] = av.z;
        As[a_k4 + 3][a_row] = av.w;
        *(float4*)&Bs[b_k][b_n4] = bv;
        __syncthreads();
#pragma unroll
        for (int kk = 0; kk < 8; kk++) {
            float a[8], bfr[8];
            *(float4*)(a)     = *(const float4*)&As[kk][ty * 8];
            *(float4*)(a + 4) = *(const float4*)&As[kk][ty * 8 + 4];
            *(float4*)(bfr)     = *(const float4*)&Bs[kk][tx * 8];
            *(float4*)(bfr + 4) = *(const float4*)&Bs[kk][tx * 8 + 4];
#pragma unroll
            for (int i = 0; i < 8; i++)
#pragma unroll
                for (int j = 0; j < 8; j++) acc[i][j] += a[i] * bfr[j];
        }
        __syncthreads();
    }
#pragma unroll
    for (int i = 0; i < 8; i++) {
        int r = row0 + ty * 8 + i;
#pragma unroll
        for (int j = 0; j < 8; j++) {
            int c = col0 + tx * 8 + j;
            float v = acc[i][j] + bias[c];
            if (EPI == 1) v = gelu_f(v);
            if (EPI == 2) v += res[(size_t)r * N + c];
            C[(size_t)r * N + c] = v;
        }
    }
}

// ---------------- SGEMM NT: C[M,N] = A[M,K] @ B[N,K]^T (no bias) ----------------
// For logits: N=50257 (guarded). M%128==0, K%8==0.
__global__ void sgemm_nt(const float* __restrict__ A, const float* __restrict__ B,
                         float* __restrict__ C, int M, int N, int K) {
    __shared__ float As[8][128];
    __shared__ float Bs[8][128];
    int tid = threadIdx.x;
    int row0 = blockIdx.y * 128, col0 = blockIdx.x * 128;
    int tx = tid & 15, ty = tid >> 4;
    int a_row = tid >> 1, a_k4 = (tid & 1) * 4;
    int b_row = tid >> 1, b_k4 = (tid & 1) * 4;
    bool bvalid = (col0 + b_row) < N;
    float acc[8][8];
#pragma unroll
    for (int i = 0; i < 8; i++)
#pragma unroll
        for (int j = 0; j < 8; j++) acc[i][j] = 0.0f;

    for (int k0 = 0; k0 < K; k0 += 8) {
        float4 av = *(const float4*)(A + (size_t)(row0 + a_row) * K + k0 + a_k4);
        float4 bv = make_float4(0.f, 0.f, 0.f, 0.f);
        if (bvalid) bv = *(const float4*)(B + (size_t)(col0 + b_row) * K + k0 + b_k4);
        As[a_k4 + 0][a_row] = av.x;
        As[a_k4 + 1][a_row] = av.y;
        As[a_k4 + 2][a_row] = av.z;
        As[a_k4 + 3][a_row] = av.w;
        Bs[b_k4 + 0][b_row] = bv.x;
        Bs[b_k4 + 1][b_row] = bv.y;
        Bs[b_k4 + 2][b_row] = bv.z;
        Bs[b_k4 + 3][b_row] = bv.w;
        __syncthreads();
#pragma unroll
        for (int kk = 0; kk < 8; kk++) {
            float a[8], bfr[8];
            *(float4*)(a)     = *(const float4*)&As[kk][ty * 8];
            *(float4*)(a + 4) = *(const float4*)&As[kk][ty * 8 + 4];
            *(float4*)(bfr)     = *(const float4*)&Bs[kk][tx * 8];
            *(float4*)(bfr + 4) = *(const float4*)&Bs[kk][tx * 8 + 4];
#pragma unroll
            for (int i = 0; i < 8; i++)
#pragma unroll
                for (int j = 0; j < 8; j++) acc[i][j] += a[i] * bfr[j];
        }
        __syncthreads();
    }
#pragma unroll
    for (int i = 0; i < 8; i++) {
        int r = row0 + ty * 8 + i;
#pragma unroll
        for (int j = 0; j < 8; j++) {
            int c = col0 + tx * 8 + j;
            if (c < N) C[(size_t)r * N + c] = acc[i][j];
        }
    }
}

// ---------------- Attention scores: sc[bh,i,j] = q.k * 0.125 (causal) ----------------
__global__ void scores_kernel(const float* __restrict__ qkv, float* __restrict__ sc) {
    int jt = blockIdx.x, it = blockIdx.y, bh = blockIdx.z;
    int i0 = it * 32, j0 = jt * 32;
    if (j0 > i0 + 31) return;                 // fully above diagonal: never read
    int b = bh / HH, h = bh % HH;
    __shared__ float Qs[32][65];
    __shared__ float Ks[32][65];
    int tx = threadIdx.x, ty = threadIdx.y;   // 32x32
    const float* qb = qkv + (size_t)(b * SS + i0 + ty) * D3 + h * HD;
    const float* kb = qkv + (size_t)(b * SS + j0 + ty) * D3 + DD + h * HD;
    Qs[ty][tx] = qb[tx];  Qs[ty][tx + 32] = qb[tx + 32];
    Ks[ty][tx] = kb[tx];  Ks[ty][tx + 32] = kb[tx + 32];
    __syncthreads();
    float acc = 0.0f;
#pragma unroll
    for (int k = 0; k < HD; k++) acc += Qs[ty][k] * Ks[tx][k];
    int i = i0 + ty, j = j0 + tx;
    sc[((size_t)bh * SS + i) * SS + j] = (j <= i) ? acc * 0.125f : -1e10f;
}

// ---------------- Softmax rows (causal; zeros above diagonal) ----------------
__global__ void softmax_kernel(float* __restrict__ sc) {
    int i = blockIdx.x, bh = blockIdx.y;
    float* row = sc + ((size_t)bh * SS + i) * SS;
    int n = i + 1;
    __shared__ float red[256];
    int tid = threadIdx.x;
    float m = -1e30f;
    for (int j = tid; j < n; j += 256) m = fmaxf(m, row[j]);
    red[tid] = m; __syncthreads();
    for (int s = 128; s > 0; s >>= 1) { if (tid < s) red[tid] = fmaxf(red[tid], red[tid + s]); __syncthreads(); }
    m = red[0];
    __syncthreads();
    float sum = 0.0f;
    for (int j = tid; j < n; j += 256) sum += __expf(row[j] - m);
    red[tid] = sum; __syncthreads();
    for (int s = 128; s > 0; s >>= 1) { if (tid < s) red[tid] += red[tid + s]; __syncthreads(); }
    float inv = 1.0f / red[0];
    for (int j = tid; j < n; j += 256) row[j] = __expf(row[j] - m) * inv;
    for (int j = n + tid; j < SS; j += 256) row[j] = 0.0f;
}

// ---------------- AV: a[b,i,h*64+d] = sum_j p[i,j] v[j,d] ----------------
__global__ void av_kernel(const float* __restrict__ qkv, const float* __restrict__ p,
                          float* __restrict__ out) {
    int it = blockIdx.x, bh = blockIdx.y;
    int b = bh / HH, h = bh % HH;
    int i0 = it * 32;
    int tid = threadIdx.x;
    int tx = tid & 63, ty = tid >> 6;          // tx: d 0..63, ty: 0..3
    __shared__ float Ps[32][33];
    __shared__ float Vs[32][64];
    float acc[8];
#pragma unroll
    for (int r = 0; r < 8; r++) acc[r] = 0.0f;
    int jmax = i0 + 32;
    for (int j0 = 0; j0 < jmax; j0 += 32) {
#pragma unroll
        for (int q = 0; q < 4; q++) {
            int idx = tid + q * 256; int r = idx >> 5, c = idx & 31;
            Ps[r][c] = p[((size_t)bh * SS + i0 + r) * SS + j0 + c];
        }
#pragma unroll
        for (int q = 0; q < 8; q++) {
            int idx = tid + q * 256; int r = idx >> 6, c = idx & 63;
            Vs[r][c] = qkv[(size_t)(b * SS + j0 + r) * D3 + 2 * DD + h * HD + c];
        }
        __syncthreads();
#pragma unroll
        for (int jj = 0; jj < 32; jj++) {
            float v = Vs[jj][tx];
#pragma unroll
            for (int r = 0; r < 8; r++) acc[r] += Ps[ty + r * 4][jj] * v;
        }
        __syncthreads();
    }
#pragma unroll
    for (int r = 0; r < 8; r++) {
        int i = i0 + ty + r * 4;
        out[(size_t)(b * SS + i) * DD + h * HD + tx] = acc[r];
    }
}

// ---------------- Orchestration ----------------
extern "C" void kernel_launch(void* const* d_in, const int* in_sizes, int n_in,
                              void* d_out, int out_size) {
    const int*   X      = (const int*)d_in[0];
    const float* wte    = (const float*)d_in[1];
    const float* wpe    = (const float*)d_in[2];
    const float* ln1_g  = (const float*)d_in[3];
    const float* ln1_b  = (const float*)d_in[4];
    const float* attn_w = (const float*)d_in[5];
    const float* attn_b = (const float*)d_in[6];
    const float* proj_w = (const float*)d_in[7];
    const float* proj_b = (const float*)d_in[8];
    const float* ln2_g  = (const float*)d_in[9];
    const float* ln2_b  = (const float*)d_in[10];
    const float* fc_w   = (const float*)d_in[11];
    const float* fc_b   = (const float*)d_in[12];
    const float* fc2_w  = (const float*)d_in[13];
    const float* fc2_b  = (const float*)d_in[14];
    const float* lnf_g  = (const float*)d_in[15];
    const float* lnf_b  = (const float*)d_in[16];
    float* out = (float*)d_out;

    float *h, *xln, *qkv, *sc, *abuf, *fcb;
    cudaGetSymbolAddress((void**)&h,    g_h);
    cudaGetSymbolAddress((void**)&xln,  g_xln);
    cudaGetSymbolAddress((void**)&qkv,  g_qkv);
    cudaGetSymbolAddress((void**)&sc,   g_scores);
    cudaGetSymbolAddress((void**)&abuf, g_abuf);
    cudaGetSymbolAddress((void**)&fcb,  g_fc);

    embed_kernel<<<BSr, 256>>>(X, wte, wpe, h);

    for (int l = 0; l < LL; l++) {
        layernorm_kernel<<<BSr, 256>>>(h, ln1_g + l * DD, ln1_b + l * DD, xln);
        sgemm_nn<0><<<dim3(D3 / 128, BSr / 128), 256>>>(
            xln, attn_w + (size_t)l * DD * D3, attn_b + (size_t)l * D3, nullptr,
            qkv, BSr, D3, DD);
        scores_kernel<<<dim3(SS / 32, SS / 32, BH), dim3(32, 32)>>>(qkv, sc);
        softmax_kernel<<<dim3(SS, BH), 256>>>(sc);
        av_kernel<<<dim3(SS / 32, BH), 256>>>(qkv, sc, abuf);
        sgemm_nn<2><<<dim3(DD / 128, BSr / 128), 256>>>(
            abuf, proj_w + (size_t)l * DD * DD, proj_b + (size_t)l * DD, h,
            h, BSr, DD, DD);
        layernorm_kernel<<<BSr, 256>>>(h, ln2_g + l * DD, ln2_b + l * DD, xln);
        sgemm_nn<1><<<dim3(D4 / 128, BSr / 128), 256>>>(
            xln, fc_w + (size_t)l * DD * D4, fc_b + (size_t)l * D4, nullptr,
            fcb, BSr, D4, DD);
        sgemm_nn<2><<<dim3(DD / 128, BSr / 128), 256>>>(
            fcb, fc2_w + (size_t)l * D4 * DD, fc2_b + (size_t)l * DD, h,
            h, BSr, DD, D4);
    }

    layernorm_kernel<<<BSr, 256>>>(h, lnf_g, lnf_b, xln);
    sgemm_nt<<<dim3((VV + 127) / 128, BSr / 128), 256>>>(xln, wte, out, BSr, VV, DD);
}

// round 2
// speedup vs baseline: 1.9768x; 1.9768x over previous
#include <cuda_runtime.h>
#include <cuda_bf16.h>
#include <math.h>
#include <stdint.h>

// ---------------- Problem constants ----------------
#define BB 2
#define SS 1024
#define DD 768
#define HH 12
#define HD 64
#define LL 4
#define VV 50257
#define BSr (BB*SS)          // 2048 rows
#define D3 (3*DD)            // 2304
#define D4 (4*DD)            // 3072
#define BH (BB*HH)           // 24

// ---------------- Scratch (device globals, no allocation) ----------------
__device__ float g_h[BSr*DD];
__device__ float g_xln[BSr*DD];
__device__ float g_qkv[BSr*D3];
__device__ float g_scores[(size_t)BH*SS*SS];   // 100 MB
__device__ float g_abuf[BSr*DD];
__device__ float g_fc[BSr*D4];

// ---------------- Helpers ----------------
__device__ __forceinline__ float gelu_f(float x) {
    const float c = 0.7978845608028654f;
    float t = tanhf(c * (x + 0.044715f * x * x * x));
    return 0.5f * x * (1.0f + t);
}

__device__ __forceinline__ uint32_t f2tf32(float x) {
    uint32_t r;
    asm("cvt.rna.tf32.f32 %0, %1;" : "=r"(r) : "f"(x));
    return r;
}

__device__ __forceinline__ void mma_tf32(float* c, const uint32_t* a, uint32_t b0, uint32_t b1) {
    asm volatile(
        "mma.sync.aligned.m16n8k8.row.col.f32.tf32.tf32.f32 "
        "{%0,%1,%2,%3}, {%4,%5,%6,%7}, {%8,%9}, {%0,%1,%2,%3};\n"
        : "+f"(c[0]), "+f"(c[1]), "+f"(c[2]), "+f"(c[3])
        : "r"(a[0]), "r"(a[1]), "r"(a[2]), "r"(a[3]), "r"(b0), "r"(b1));
}

// ---------------- Embedding ----------------
__global__ void embed_kernel(const int* __restrict__ X, const float* __restrict__ wte,
                             const float* __restrict__ wpe, float* __restrict__ h) {
    int bs = blockIdx.x;
    int s = bs & (SS - 1);
    int tok = X[bs];
    const float* we = wte + (size_t)tok * DD;
    const float* wp = wpe + (size_t)s * DD;
    float* out = h + (size_t)bs * DD;
    int tid = threadIdx.x;
#pragma unroll
    for (int q = 0; q < 3; q++) {
        int d = tid + q * 256;
        out[d] = we[d] + wp[d];
    }
}

// ---------------- LayerNorm ----------------
__global__ void layernorm_kernel(const float* __restrict__ in, const float* __restrict__ g,
                                 const float* __restrict__ b, float* __restrict__ out) {
    int r = blockIdx.x;
    int tid = threadIdx.x;
    const float* x = in + (size_t)r * DD;
    float v0 = x[tid], v1 = x[tid + 256], v2 = x[tid + 512];
    __shared__ float red[256];
    red[tid] = v0 + v1 + v2;
    __syncthreads();
    for (int s = 128; s > 0; s >>= 1) { if (tid < s) red[tid] += red[tid + s]; __syncthreads(); }
    float m = red[0] * (1.0f / DD);
    __syncthreads();
    float d0 = v0 - m, d1 = v1 - m, d2 = v2 - m;
    red[tid] = d0 * d0 + d1 * d1 + d2 * d2;
    __syncthreads();
    for (int s = 128; s > 0; s >>= 1) { if (tid < s) red[tid] += red[tid + s]; __syncthreads(); }
    float inv = rsqrtf(red[0] * (1.0f / DD) + 1e-5f);
    float* o = out + (size_t)r * DD;
    o[tid]       = d0 * inv * g[tid]       + b[tid];
    o[tid + 256] = d1 * inv * g[tid + 256] + b[tid + 256];
    o[tid + 512] = d2 * inv * g[tid + 512] + b[tid + 512];
}

// ---------------- TF32 tensor-core GEMM ----------------
// C[M,N] = A[M,K] @ op(B) + epilogue.
// NT=false: B is [K,N] row-major.  NT=true: B is [N,K] row-major (B^T effect).
// Block tile 128x128, BK=32, 256 threads = 8 warps (4 along M x 2 along N),
// warp tile 32x64 -> 2(M) x 8(N) m16n8k8 tiles, 4 k-steps per BK.
// EPI: 0=bias, 1=bias+gelu, 2=bias+residual, 3=none
// GUARD: guard N dimension (cols) for B loads and C stores.
template <int EPI, bool NT, bool GUARD>
__global__ void __launch_bounds__(256)
mma_gemm(const float* __restrict__ A, const float* __restrict__ B,
         const float* __restrict__ bias, const float* __restrict__ res,
         float* __restrict__ C, int M, int N, int K) {
    __shared__ uint32_t As[128][36];   // [m][k], pad 4
    __shared__ uint32_t Bs[32][136];   // [k][n], pad 8

    int tid = threadIdx.x;
    int lane = tid & 31;
    int warp = tid >> 5;
    int gid = lane >> 2;     // groupID 0..7
    int tig = lane & 3;      // thread-in-group 0..3
    int warp_m = warp & 3;   // 0..3 -> rows warp_m*32
    int warp_n = warp >> 2;  // 0..1 -> cols warp_n*64

    int row0 = blockIdx.y * 128;
    int col0 = blockIdx.x * 128;

    // A tile load mapping: 2 threads per row, 16 floats each
    int a_row = tid >> 1;
    int a_k   = (tid & 1) * 16;
    // B tile (NN): 8 threads per k-row, 16 floats along n
    int b_k   = tid >> 3;
    int b_n   = (tid & 7) * 16;
    // B tile (NT): thread owns one n (row of B), 16 floats along k
    int bt_n  = tid >> 1;
    int bt_k  = (tid & 1) * 16;
    bool bt_valid = !GUARD || (col0 + bt_n) < N;

    float acc[2][8][4];
#pragma unroll
    for (int mi = 0; mi < 2; mi++)
#pragma unroll
        for (int ni = 0; ni < 8; ni++)
#pragma unroll
            for (int e = 0; e < 4; e++) acc[mi][ni][e] = 0.0f;

    for (int k0 = 0; k0 < K; k0 += 32) {
        // gmem -> regs
        float4 ar[4];
#pragma unroll
        for (int j = 0; j < 4; j++)
            ar[j] = *(const float4*)(A + (size_t)(row0 + a_row) * K + k0 + a_k + 4 * j);
        float4 br[4];
        if (NT) {
#pragma unroll
            for (int j = 0; j < 4; j++) {
                br[j] = make_float4(0.f, 0.f, 0.f, 0.f);
                if (bt_valid)
                    br[j] = *(const float4*)(B + (size_t)(col0 + bt_n) * K + k0 + bt_k + 4 * j);
            }
        } else {
#pragma unroll
            for (int j = 0; j < 4; j++)
                br[j] = *(const float4*)(B + (size_t)(k0 + b_k) * N + col0 + b_n + 4 * j);
        }

        __syncthreads();   // previous iteration's compute done

        // regs -> smem (convert to tf32)
#pragma unroll
        for (int j = 0; j < 4; j++) {
            As[a_row][a_k + 4 * j + 0] = f2tf32(ar[j].x);
            As[a_row][a_k + 4 * j + 1] = f2tf32(ar[j].y);
            As[a_row][a_k + 4 * j + 2] = f2tf32(ar[j].z);
            As[a_row][a_k + 4 * j + 3] = f2tf32(ar[j].w);
        }
        if (NT) {
#pragma unroll
            for (int j = 0; j < 4; j++) {
                Bs[bt_k + 4 * j + 0][bt_n] = f2tf32(br[j].x);
                Bs[bt_k + 4 * j + 1][bt_n] = f2tf32(br[j].y);
                Bs[bt_k + 4 * j + 2][bt_n] = f2tf32(br[j].z);
                Bs[bt_k + 4 * j + 3][bt_n] = f2tf32(br[j].w);
            }
        } else {
#pragma unroll
            for (int j = 0; j < 4; j++) {
                Bs[b_k][b_n + 4 * j + 0] = f2tf32(br[j].x);
                Bs[b_k][b_n + 4 * j + 1] = f2tf32(br[j].y);
                Bs[b_k][b_n + 4 * j + 2] = f2tf32(br[j].z);
                Bs[b_k][b_n + 4 * j + 3] = f2tf32(br[j].w);
            }
        }
        __syncthreads();

        // compute 4 x k8 steps
#pragma unroll
        for (int kk = 0; kk < 4; kk++) {
            int k8 = kk * 8;
            uint32_t af[2][4];
#pragma unroll
            for (int mi = 0; mi < 2; mi++) {
                int rb = warp_m * 32 + mi * 16;
                af[mi][0] = As[rb + gid][k8 + tig];
                af[mi][1] = As[rb + gid + 8][k8 + tig];
                af[mi][2] = As[rb + gid][k8 + tig + 4];
                af[mi][3] = As[rb + gid + 8][k8 + tig + 4];
            }
#pragma unroll
            for (int ni = 0; ni < 8; ni++) {
                int cb = warp_n * 64 + ni * 8;
                uint32_t b0 = Bs[k8 + tig][cb + gid];
                uint32_t b1 = Bs[k8 + tig + 4][cb + gid];
#pragma unroll
                for (int mi = 0; mi < 2; mi++)
                    mma_tf32(acc[mi][ni], af[mi], b0, b1);
            }
        }
    }

    // Epilogue
    int row_w = row0 + warp_m * 32;
    int col_w = col0 + warp_n * 64;
#pragma unroll
    for (int mi = 0; mi < 2; mi++) {
        int r0 = row_w + mi * 16 + gid;
        int r1 = r0 + 8;
#pragma unroll
        for (int ni = 0; ni < 8; ni++) {
            int c0 = col_w + ni * 8 + tig * 2;
#pragma unroll
            for (int e = 0; e < 4; e++) {
                int r = (e < 2) ? r0 : r1;
                int c = c0 + (e & 1);
                if (GUARD && c >= N) continue;
                float v = acc[mi][ni][e];
                if (EPI != 3) v += bias[c];
                if (EPI == 1) v = gelu_f(v);
                if (EPI == 2) v += res[(size_t)r * N + c];
                C[(size_t)r * N + c] = v;
            }
        }
    }
}

// ---------------- Attention scores (fp32, causal) ----------------
__global__ void scores_kernel(const float* __restrict__ qkv, float* __restrict__ sc) {
    int jt = blockIdx.x, it = blockIdx.y, bh = blockIdx.z;
    int i0 = it * 32, j0 = jt * 32;
    if (j0 > i0 + 31) return;
    int b = bh / HH, h = bh % HH;
    __shared__ float Qs[32][65];
    __shared__ float Ks[32][65];
    int tx = threadIdx.x, ty = threadIdx.y;
    const float* qb = qkv + (size_t)(b * SS + i0 + ty) * D3 + h * HD;
    const float* kb = qkv + (size_t)(b * SS + j0 + ty) * D3 + DD + h * HD;
    Qs[ty][tx] = qb[tx];  Qs[ty][tx + 32] = qb[tx + 32];
    Ks[ty][tx] = kb[tx];  Ks[ty][tx + 32] = kb[tx + 32];
    __syncthreads();
    float acc = 0.0f;
#pragma unroll
    for (int k = 0; k < HD; k++) acc += Qs[ty][k] * Ks[tx][k];
    int i = i0 + ty, j = j0 + tx;
    sc[((size_t)bh * SS + i) * SS + j] = (j <= i) ? acc * 0.125f : -1e10f;
}

// ---------------- Softmax rows (causal; zeros above diagonal) ----------------
__global__ void softmax_kernel(float* __restrict__ sc) {
    int i = blockIdx.x, bh = blockIdx.y;
    float* row = sc + ((size_t)bh * SS + i) * SS;
    int n = i + 1;
    __shared__ float red[256];
    int tid = threadIdx.x;
    float m = -1e30f;
    for (int j = tid; j < n; j += 256) m = fmaxf(m, row[j]);
    red[tid] = m; __syncthreads();
    for (int s = 128; s > 0; s >>= 1) { if (tid < s) red[tid] = fmaxf(red[tid], red[tid + s]); __syncthreads(); }
    m = red[0];
    __syncthreads();
    float sum = 0.0f;
    for (int j = tid; j < n; j += 256) sum += __expf(row[j] - m);
    red[tid] = sum; __syncthreads();
    for (int s = 128; s > 0; s >>= 1) { if (tid < s) red[tid] += red[tid + s]; __syncthreads(); }
    float inv = 1.0f / red[0];
    for (int j = tid; j < n; j += 256) row[j] = __expf(row[j] - m) * inv;
    for (int j = n + tid; j < SS; j += 256) row[j] = 0.0f;
}

// ---------------- AV ----------------
__global__ void av_kernel(const float* __restrict__ qkv, const float* __restrict__ p,
                          float* __restrict__ out) {
    int it = blockIdx.x, bh = blockIdx.y;
    int b = bh / HH, h = bh % HH;
    int i0 = it * 32;
    int tid = threadIdx.x;
    int tx = tid & 63, ty = tid >> 6;
    __shared__ float Ps[32][33];
    __shared__ float Vs[32][64];
    float acc[8];
#pragma unroll
    for (int r = 0; r < 8; r++) acc[r] = 0.0f;
    int jmax = i0 + 32;
    for (int j0 = 0; j0 < jmax; j0 += 32) {
#pragma unroll
        for (int q = 0; q < 4; q++) {
            int idx = tid + q * 256; int r = idx >> 5, c = idx & 31;
            Ps[r][c] = p[((size_t)bh * SS + i0 + r) * SS + j0 + c];
        }
#pragma unroll
        for (int q = 0; q < 8; q++) {
            int idx = tid + q * 256; int r = idx >> 6, c = idx & 63;
            Vs[r][c] = qkv[(size_t)(b * SS + j0 + r) * D3 + 2 * DD + h * HD + c];
        }
        __syncthreads();
#pragma unroll
        for (int jj = 0; jj < 32; jj++) {
            float v = Vs[jj][tx];
#pragma unroll
            for (int r = 0; r < 8; r++) acc[r] += Ps[ty + r * 4][jj] * v;
        }
        __syncthreads();
    }
#pragma unroll
    for (int r = 0; r < 8; r++) {
        int i = i0 + ty + r * 4;
        out[(size_t)(b * SS + i) * DD + h * HD + tx] = acc[r];
    }
}

// ---------------- Orchestration ----------------
extern "C" void kernel_launch(void* const* d_in, const int* in_sizes, int n_in,
                              void* d_out, int out_size) {
    const int*   X      = (const int*)d_in[0];
    const float* wte    = (const float*)d_in[1];
    const float* wpe    = (const float*)d_in[2];
    const float* ln1_g  = (const float*)d_in[3];
    const float* ln1_b  = (const float*)d_in[4];
    const float* attn_w = (const float*)d_in[5];
    const float* attn_b = (const float*)d_in[6];
    const float* proj_w = (const float*)d_in[7];
    const float* proj_b = (const float*)d_in[8];
    const float* ln2_g  = (const float*)d_in[9];
    const float* ln2_b  = (const float*)d_in[10];
    const float* fc_w   = (const float*)d_in[11];
    const float* fc_b   = (const float*)d_in[12];
    const float* fc2_w  = (const float*)d_in[13];
    const float* fc2_b  = (const float*)d_in[14];
    const float* lnf_g  = (const float*)d_in[15];
    const float* lnf_b  = (const float*)d_in[16];
    float* out = (float*)d_out;

    float *h, *xln, *qkv, *sc, *abuf, *fcb;
    cudaGetSymbolAddress((void**)&h,    g_h);
    cudaGetSymbolAddress((void**)&xln,  g_xln);
    cudaGetSymbolAddress((void**)&qkv,  g_qkv);
    cudaGetSymbolAddress((void**)&sc,   g_scores);
    cudaGetSymbolAddress((void**)&abuf, g_abuf);
    cudaGetSymbolAddress((void**)&fcb,  g_fc);

    embed_kernel<<<BSr, 256>>>(X, wte, wpe, h);

    for (int l = 0; l < LL; l++) {
        layernorm_kernel<<<BSr, 256>>>(h, ln1_g + l * DD, ln1_b + l * DD, xln);
        mma_gemm<0, false, false><<<dim3(D3 / 128, BSr / 128), 256>>>(
            xln, attn_w + (size_t)l * DD * D3, attn_b + (size_t)l * D3, nullptr,
            qkv, BSr, D3, DD);
        scores_kernel<<<dim3(SS / 32, SS / 32, BH), dim3(32, 32)>>>(qkv, sc);
        softmax_kernel<<<dim3(SS, BH), 256>>>(sc);
        av_kernel<<<dim3(SS / 32, BH), 256>>>(qkv, sc, abuf);
        mma_gemm<2, false, false><<<dim3(DD / 128, BSr / 128), 256>>>(
            abuf, proj_w + (size_t)l * DD * DD, proj_b + (size_t)l * DD, h,
            h, BSr, DD, DD);
        layernorm_kernel<<<BSr, 256>>>(h, ln2_g + l * DD, ln2_b + l * DD, xln);
        mma_gemm<1, false, false><<<dim3(D4 / 128, BSr / 128), 256>>>(
            xln, fc_w + (size_t)l * DD * D4, fc_b + (size_t)l * D4, nullptr,
            fcb, BSr, D4, DD);
        mma_gemm<2, false, false><<<dim3(DD / 128, BSr / 128), 256>>>(
            fcb, fc2_w + (size_t)l * D4 * DD, fc2_b + (size_t)l * DD, h,
            h, BSr, DD, D4);
    }

    layernorm_kernel<<<BSr, 256>>>(h, lnf_g, lnf_b, xln);
    mma_gemm<3, true, true><<<dim3((VV + 127) / 128, BSr / 128), 256>>>(
        xln, wte, nullptr, nullptr, out, BSr, VV, DD);
}

// round 3
// speedup vs baseline: 3.3557x; 1.6976x over previous
#include <cuda_runtime.h>
#include <cuda_bf16.h>
#include <math.h>
#include <stdint.h>

// ---------------- Problem constants ----------------
#define BB 2
#define SS 1024
#define DD 768
#define HH 12
#define HD 64
#define LL 4
#define VV 50257
#define BSr (BB*SS)          // 2048
#define D3 (3*DD)            // 2304
#define D4 (4*DD)            // 3072
#define BH (BB*HH)           // 24

// Rounded-weight scratch offsets (floats)
#define OFF_ATTN 0
#define N_ATTN   (LL*DD*D3)          // 7,077,888
#define OFF_PROJ (OFF_ATTN + N_ATTN)
#define N_PROJ   (LL*DD*DD)          // 2,359,296
#define OFF_FC   (OFF_PROJ + N_PROJ)
#define N_FC     (LL*DD*D4)          // 9,437,184
#define OFF_FC2  (OFF_FC + N_FC)
#define N_FC2    (LL*D4*DD)          // 9,437,184
#define OFF_WTE  (OFF_FC2 + N_FC2)
#define N_WTE    (VV*DD)             // 38,597,376
#define N_WRND   (OFF_WTE + N_WTE)   // 66,908,928

// ---------------- Scratch (device globals) ----------------
__device__ float g_h[BSr*DD];
__device__ float g_xln[BSr*DD];
__device__ float g_qkv[BSr*D3];
__device__ float g_abuf[BSr*DD];
__device__ float g_fc[BSr*D4];
__device__ float g_wrnd[N_WRND];

// ---------------- Helpers ----------------
__device__ __forceinline__ float gelu_f(float x) {
    const float c = 0.7978845608028654f;
    float t = tanhf(c * (x + 0.044715f * x * x * x));
    return 0.5f * x * (1.0f + t);
}

__device__ __forceinline__ uint32_t f2tf32(float x) {
    uint32_t r;
    asm("cvt.rna.tf32.f32 %0, %1;" : "=r"(r) : "f"(x));
    return r;
}
__device__ __forceinline__ float tf32rn(float x) { return __uint_as_float(f2tf32(x)); }

__device__ __forceinline__ void mma_tf32(float* c, const uint32_t* a, uint32_t b0, uint32_t b1) {
    asm volatile(
        "mma.sync.aligned.m16n8k8.row.col.f32.tf32.tf32.f32 "
        "{%0,%1,%2,%3}, {%4,%5,%6,%7}, {%8,%9}, {%0,%1,%2,%3};\n"
        : "+f"(c[0]), "+f"(c[1]), "+f"(c[2]), "+f"(c[3])
        : "r"(a[0]), "r"(a[1]), "r"(a[2]), "r"(a[3]), "r"(b0), "r"(b1));
}

__device__ __forceinline__ void cpa16(void* dst, const void* src, int srcbytes) {
    uint32_t d = (uint32_t)__cvta_generic_to_shared(dst);
    asm volatile("cp.async.ca.shared.global [%0], [%1], 16, %2;\n"
                 :: "r"(d), "l"(src), "r"(srcbytes));
}

// ---------------- Preround weights to tf32 ----------------
__global__ void preround_kernel(const float* __restrict__ src, float* __restrict__ dst, int n4) {
    int i = blockIdx.x * blockDim.x + threadIdx.x;
    int stride = gridDim.x * blockDim.x;
    for (; i < n4; i += stride) {
        float4 v = ((const float4*)src)[i];
        v.x = tf32rn(v.x); v.y = tf32rn(v.y); v.z = tf32rn(v.z); v.w = tf32rn(v.w);
        ((float4*)dst)[i] = v;
    }
}

// ---------------- Embedding ----------------
__global__ void embed_kernel(const int* __restrict__ X, const float* __restrict__ wte,
                             const float* __restrict__ wpe, float* __restrict__ h) {
    int bs = blockIdx.x;
    int s = bs & (SS - 1);
    int tok = X[bs];
    const float* we = wte + (size_t)tok * DD;
    const float* wp = wpe + (size_t)s * DD;
    float* out = h + (size_t)bs * DD;
    int tid = threadIdx.x;
#pragma unroll
    for (int q = 0; q < 3; q++) {
        int d = tid + q * 256;
        out[d] = we[d] + wp[d];
    }
}

// ---------------- LayerNorm (rounds output to tf32 for GEMM consumers) ----------------
__global__ void layernorm_kernel(const float* __restrict__ in, const float* __restrict__ g,
                                 const float* __restrict__ b, float* __restrict__ out) {
    int r = blockIdx.x;
    int tid = threadIdx.x;
    const float* x = in + (size_t)r * DD;
    float v0 = x[tid], v1 = x[tid + 256], v2 = x[tid + 512];
    __shared__ float red[256];
    red[tid] = v0 + v1 + v2;
    __syncthreads();
    for (int s = 128; s > 0; s >>= 1) { if (tid < s) red[tid] += red[tid + s]; __syncthreads(); }
    float m = red[0] * (1.0f / DD);
    __syncthreads();
    float d0 = v0 - m, d1 = v1 - m, d2 = v2 - m;
    red[tid] = d0 * d0 + d1 * d1 + d2 * d2;
    __syncthreads();
    for (int s = 128; s > 0; s >>= 1) { if (tid < s) red[tid] += red[tid + s]; __syncthreads(); }
    float inv = rsqrtf(red[0] * (1.0f / DD) + 1e-5f);
    float* o = out + (size_t)r * DD;
    o[tid]       = tf32rn(d0 * inv * g[tid]       + b[tid]);
    o[tid + 256] = tf32rn(d1 * inv * g[tid + 256] + b[tid + 256]);
    o[tid + 512] = tf32rn(d2 * inv * g[tid + 512] + b[tid + 512]);
}

// ---------------- Pipelined TF32 tensor-core GEMM ----------------
// Inputs MUST already be tf32-rounded (raw bits fed to mma).
// Block 128x128, BK=16, double-buffered cp.async, 256 threads = 8 warps.
// EPI: 0=bias+round, 1=bias+gelu+round, 2=bias+residual (no round), 3=plain
// NT: B is [N,K] row-major (logits). GUARD: guard N for B loads + C stores.
// For NT, grid is (row_tiles, col_tiles) so col-sharing blocks are adjacent.
template <int EPI, bool NT, bool GUARD>
__global__ void __launch_bounds__(256, 2)
mma_gemm(const float* __restrict__ A, const float* __restrict__ B,
         const float* __restrict__ bias, const float* __restrict__ res,
         float* __restrict__ C, int M, int N, int K) {
    __shared__ float As[2][128][20];
    __shared__ float Bs[2][NT ? (128 * 20) : (16 * 132)];

    int tid = threadIdx.x;
    int lane = tid & 31;
    int warp = tid >> 5;
    int gid = lane >> 2, tig = lane & 3;
    int warp_m = warp & 3, warp_n = warp >> 2;
    int row_blk = NT ? blockIdx.x : blockIdx.y;
    int col_blk = NT ? blockIdx.y : blockIdx.x;
    int row0 = row_blk * 128, col0 = col_blk * 128;

    float acc[2][8][4];
#pragma unroll
    for (int mi = 0; mi < 2; mi++)
#pragma unroll
        for (int ni = 0; ni < 8; ni++)
#pragma unroll
            for (int e = 0; e < 4; e++) acc[mi][ni][e] = 0.0f;

    auto stage = [&](int buf, int k0) {
#pragma unroll
        for (int q = 0; q < 2; q++) {
            int cid = tid + q * 256;
            int ar = cid >> 2, akc = (cid & 3) * 4;
            cpa16(&As[buf][ar][akc], A + (size_t)(row0 + ar) * K + k0 + akc, 16);
            if (NT) {
                int bn = cid >> 2, bkc = (cid & 3) * 4;
                bool ok = (!GUARD) || (col0 + bn) < N;
                const float* src = ok ? (B + (size_t)(col0 + bn) * K + k0 + bkc) : B;
                cpa16(&Bs[buf][bn * 20 + bkc], src, ok ? 16 : 0);
            } else {
                int bk = cid >> 5, bnc = (cid & 31) * 4;
                cpa16(&Bs[buf][bk * 132 + bnc], B + (size_t)(k0 + bk) * N + col0 + bnc, 16);
            }
        }
        asm volatile("cp.async.commit_group;\n");
    };

    auto compute = [&](int buf) {
#pragma unroll
        for (int kk = 0; kk < 2; kk++) {
            int k8 = kk * 8;
            uint32_t af[2][4];
#pragma unroll
            for (int mi = 0; mi < 2; mi++) {
                int rb = warp_m * 32 + mi * 16;
                af[mi][0] = __float_as_uint(As[buf][rb + gid][k8 + tig]);
                af[mi][1] = __float_as_uint(As[buf][rb + gid + 8][k8 + tig]);
                af[mi][2] = __float_as_uint(As[buf][rb + gid][k8 + tig + 4]);
                af[mi][3] = __float_as_uint(As[buf][rb + gid + 8][k8 + tig + 4]);
            }
#pragma unroll
            for (int ni = 0; ni < 8; ni++) {
                int cb = warp_n * 64 + ni * 8;
                uint32_t b0, b1;
                if (NT) {
                    b0 = __float_as_uint(Bs[buf][(cb + gid) * 20 + k8 + tig]);
                    b1 = __float_as_uint(Bs[buf][(cb + gid) * 20 + k8 + tig + 4]);
                } else {
                    b0 = __float_as_uint(Bs[buf][(k8 + tig) * 132 + cb + gid]);
                    b1 = __float_as_uint(Bs[buf][(k8 + tig + 4) * 132 + cb + gid]);
                }
                mma_tf32(acc[0][ni], af[0], b0, b1);
                mma_tf32(acc[1][ni], af[1], b0, b1);
            }
        }
    };

    int nIter = K >> 4;
    stage(0, 0);
    for (int i2 = 0; i2 < nIter; i2++) {
        int buf = i2 & 1;
        if (i2 + 1 < nIter) {
            stage(buf ^ 1, (i2 + 1) << 4);
            asm volatile("cp.async.wait_group 1;\n");
        } else {
            asm volatile("cp.async.wait_group 0;\n");
        }
        __syncthreads();
        compute(buf);
        __syncthreads();
    }

    // Epilogue
    int row_w = row0 + warp_m * 32;
    int col_w = col0 + warp_n * 64;
#pragma unroll
    for (int mi = 0; mi < 2; mi++) {
        int r0 = row_w + mi * 16 + gid;
        int r1 = r0 + 8;
#pragma unroll
        for (int ni = 0; ni < 8; ni++) {
            int c0 = col_w + ni * 8 + tig * 2;
#pragma unroll
            for (int e = 0; e < 4; e++) {
                int r = (e < 2) ? r0 : r1;
                int c = c0 + (e & 1);
                if (GUARD && c >= N) continue;
                float v = acc[mi][ni][e];
                if (EPI == 0) v = tf32rn(v + bias[c]);
                if (EPI == 1) v = tf32rn(gelu_f(v + bias[c]));
                if (EPI == 2) v = v + bias[c] + res[(size_t)r * N + c];
                C[(size_t)r * N + c] = v;
            }
        }
    }
}

// ---------------- Fused flash attention ----------------
// Block = (64 query rows, 1 head). 128 threads = 4 warps, 16 rows/warp.
// tf32 mma for QK^T and PV, fp32 online softmax. qkv pre-rounded to tf32.
// Smem swizzle: element [r][c] stored at [r][(c + 4r) & 63] — conflict-free
// for both natural row stores and mma B-fragment reads.
__global__ void __launch_bounds__(128) flash_kernel(const float* __restrict__ qkv,
                                                    float* __restrict__ out) {
    int it = blockIdx.x, bh = blockIdx.y;
    int b = bh / HH, h = bh % HH;
    int i0 = it * 64;
    int tid = threadIdx.x, lane = tid & 31, warp = tid >> 5;
    int gid = lane >> 2, tig = lane & 3;

    __shared__ float Qs[64][64];
    __shared__ float Ks[64][64];
    __shared__ float Vs[64][64];

    // Load Q tile (swizzled)
#pragma unroll
    for (int q = 0; q < 8; q++) {
        int cid = tid + q * 128;
        int r = cid >> 4, c4 = (cid & 15) * 4;
        float4 v = *(const float4*)(qkv + (size_t)(b * SS + i0 + r) * D3 + h * HD + c4);
        *(float4*)&Qs[r][(c4 + 4 * r) & 63] = v;
    }
    __syncthreads();

    // Q fragments to registers (reused across all j-tiles)
    uint32_t qa[8][4];
    int r0 = warp * 16 + gid;
#pragma unroll
    for (int ks = 0; ks < 8; ks++) {
        int k = ks * 8;
        qa[ks][0] = __float_as_uint(Qs[r0][((k + tig) + 4 * r0) & 63]);
        qa[ks][1] = __float_as_uint(Qs[r0 + 8][((k + tig) + 4 * (r0 + 8)) & 63]);
        qa[ks][2] = __float_as_uint(Qs[r0][((k + tig + 4) + 4 * r0) & 63]);
        qa[ks][3] = __float_as_uint(Qs[r0 + 8][((k + tig + 4) + 4 * (r0 + 8)) & 63]);
    }

    float oacc[8][4];
#pragma unroll
    for (int nt = 0; nt < 8; nt++)
#pragma unroll
        for (int e = 0; e < 4; e++) oacc[nt][e] = 0.0f;
    float m_run[2] = {-1e30f, -1e30f};
    float l_run[2] = {0.0f, 0.0f};

    for (int j0 = 0; j0 <= i0; j0 += 64) {
        __syncthreads();   // previous iteration's K/V reads done (also orders Q reads)
        // Load K, V tiles (swizzled, natural row layout)
#pragma unroll
        for (int q = 0; q < 8; q++) {
            int cid = tid + q * 128;
            int r = cid >> 4, c4 = (cid & 15) * 4;
            const float* kp = qkv + (size_t)(b * SS + j0 + r) * D3 + DD + h * HD + c4;
            *(float4*)&Ks[r][(c4 + 4 * r) & 63] = *(const float4*)kp;
            *(float4*)&Vs[r][(c4 + 4 * r) & 63] = *(const float4*)(kp + DD);
        }
        __syncthreads();

        // S = Q K^T
        float sacc[8][4];
#pragma unroll
        for (int nt = 0; nt < 8; nt++)
#pragma unroll
            for (int e = 0; e < 4; e++) sacc[nt][e] = 0.0f;
#pragma unroll
        for (int ks = 0; ks < 8; ks++) {
            int k8 = ks * 8;
#pragma unroll
            for (int nt = 0; nt < 8; nt++) {
                int n0 = nt * 8 + gid;
                uint32_t b0 = __float_as_uint(Ks[n0][((k8 + tig) + 4 * n0) & 63]);
                uint32_t b1 = __float_as_uint(Ks[n0][((k8 + tig + 4) + 4 * n0) & 63]);
                mma_tf32(sacc[nt], qa[ks], b0, b1);
            }
        }

        // scale + causal mask (diagonal tile only)
        bool diag = (j0 == i0);
#pragma unroll
        for (int nt = 0; nt < 8; nt++)
#pragma unroll
            for (int e = 0; e < 4; e++) {
                float s = sacc[nt][e] * 0.125f;
                if (diag) {
                    int rr = warp * 16 + gid + (e >> 1) * 8;
                    int cc = nt * 8 + tig * 2 + (e & 1);
                    if (cc > rr) s = -1e10f;
                }
                sacc[nt][e] = s;
            }

        // online softmax (per row-half: 0 -> rows gid, 1 -> rows gid+8)
        float mloc[2] = {-1e30f, -1e30f};
#pragma unroll
        for (int nt = 0; nt < 8; nt++)
#pragma unroll
            for (int e = 0; e < 4; e++) mloc[e >> 1] = fmaxf(mloc[e >> 1], sacc[nt][e]);
#pragma unroll
        for (int hh = 0; hh < 2; hh++) {
            mloc[hh] = fmaxf(mloc[hh], __shfl_xor_sync(0xffffffffu, mloc[hh], 1));
            mloc[hh] = fmaxf(mloc[hh], __shfl_xor_sync(0xffffffffu, mloc[hh], 2));
        }
        float mnew[2] = {fmaxf(m_run[0], mloc[0]), fmaxf(m_run[1], mloc[1])};
        float al[2] = {__expf(m_run[0] - mnew[0]), __expf(m_run[1] - mnew[1])};

        float psum[2] = {0.0f, 0.0f};
#pragma unroll
        for (int nt = 0; nt < 8; nt++)
#pragma unroll
            for (int e = 0; e < 4; e++) {
                float p = __expf(sacc[nt][e] - mnew[e >> 1]);
                sacc[nt][e] = p;
                psum[e >> 1] += p;
            }
#pragma unroll
        for (int hh = 0; hh < 2; hh++) {
            psum[hh] += __shfl_xor_sync(0xffffffffu, psum[hh], 1);
            psum[hh] += __shfl_xor_sync(0xffffffffu, psum[hh], 2);
            l_run[hh] = l_run[hh] * al[hh] + psum[hh];
            m_run[hh] = mnew[hh];
        }
#pragma unroll
        for (int nt = 0; nt < 8; nt++)
#pragma unroll
            for (int e = 0; e < 4; e++) oacc[nt][e] *= al[e >> 1];

        // P (C-layout) -> A-fragments via shuffles, then O += P V
        int src1 = (gid << 2) + (tig >> 1);
        int src2 = src1 + 2;
#pragma unroll
        for (int ks = 0; ks < 8; ks++) {
            float c0 = sacc[ks][0], c1 = sacc[ks][1], c2 = sacc[ks][2], c3 = sacc[ks][3];
            float v00 = __shfl_sync(0xffffffffu, c0, src1);
            float v01 = __shfl_sync(0xffffffffu, c1, src1);
            float v02 = __shfl_sync(0xffffffffu, c0, src2);
            float v03 = __shfl_sync(0xffffffffu, c1, src2);
            float v10 = __shfl_sync(0xffffffffu, c2, src1);
            float v11 = __shfl_sync(0xffffffffu, c3, src1);
            float v12 = __shfl_sync(0xffffffffu, c2, src2);
            float v13 = __shfl_sync(0xffffffffu, c3, src2);
            uint32_t pa[4];
            bool oddt = (tig & 1);
            pa[0] = f2tf32(oddt ? v01 : v00);
            pa[1] = f2tf32(oddt ? v11 : v10);
            pa[2] = f2tf32(oddt ? v03 : v02);
            pa[3] = f2tf32(oddt ? v13 : v12);
            int k8 = ks * 8;
            int kr0 = k8 + tig, kr1 = k8 + tig + 4;
#pragma unroll
            for (int nt = 0; nt < 8; nt++) {
                int n0 = nt * 8 + gid;
                uint32_t b0 = __float_as_uint(Vs[kr0][(n0 + 4 * kr0) & 63]);
                uint32_t b1 = __float_as_uint(Vs[kr1][(n0 + 4 * kr1) & 63]);
                mma_tf32(oacc[nt], pa, b0, b1);
            }
        }
    }

    // Epilogue: normalize, round to tf32 (feeds proj GEMM), store
    float inv[2] = {1.0f / l_run[0], 1.0f / l_run[1]};
#pragma unroll
    for (int nt = 0; nt < 8; nt++)
#pragma unroll
        for (int e = 0; e < 4; e++) {
            int i = i0 + warp * 16 + gid + (e >> 1) * 8;
            int d = nt * 8 + tig * 2 + (e & 1);
            float v = oacc[nt][e] * inv[e >> 1];
            out[(size_t)(b * SS + i) * DD + h * HD + d] = tf32rn(v);
        }
}

// ---------------- Orchestration ----------------
extern "C" void kernel_launch(void* const* d_in, const int* in_sizes, int n_in,
                              void* d_out, int out_size) {
    const int*   X      = (const int*)d_in[0];
    const float* wte    = (const float*)d_in[1];
    const float* wpe    = (const float*)d_in[2];
    const float* ln1_g  = (const float*)d_in[3];
    const float* ln1_b  = (const float*)d_in[4];
    const float* attn_w = (const float*)d_in[5];
    const float* attn_b = (const float*)d_in[6];
    const float* proj_w = (const float*)d_in[7];
    const float* proj_b = (const float*)d_in[8];
    const float* ln2_g  = (const float*)d_in[9];
    const float* ln2_b  = (const float*)d_in[10];
    const float* fc_w   = (const float*)d_in[11];
    const float* fc_b   = (const float*)d_in[12];
    const float* fc2_w  = (const float*)d_in[13];
    const float* fc2_b  = (const float*)d_in[14];
    const float* lnf_g  = (const float*)d_in[15];
    const float* lnf_b  = (const float*)d_in[16];
    float* out = (float*)d_out;

    float *h, *xln, *qkv, *abuf, *fcb, *wr;
    cudaGetSymbolAddress((void**)&h,    g_h);
    cudaGetSymbolAddress((void**)&xln,  g_xln);
    cudaGetSymbolAddress((void**)&qkv,  g_qkv);
    cudaGetSymbolAddress((void**)&abuf, g_abuf);
    cudaGetSymbolAddress((void**)&fcb,  g_fc);
    cudaGetSymbolAddress((void**)&wr,   g_wrnd);

    // Pre-round all weights to tf32 (RN) so GEMMs feed raw bits to mma
    preround_kernel<<<2048, 256>>>(attn_w, wr + OFF_ATTN, N_ATTN / 4);
    preround_kernel<<<2048, 256>>>(proj_w, wr + OFF_PROJ, N_PROJ / 4);
    preround_kernel<<<2048, 256>>>(fc_w,   wr + OFF_FC,   N_FC / 4);
    preround_kernel<<<2048, 256>>>(fc2_w,  wr + OFF_FC2,  N_FC2 / 4);
    preround_kernel<<<4096, 256>>>(wte,    wr + OFF_WTE,  N_WTE / 4);

    embed_kernel<<<BSr, 256>>>(X, wte, wpe, h);

    for (int l = 0; l < LL; l++) {
        layernorm_kernel<<<BSr, 256>>>(h, ln1_g + l * DD, ln1_b + l * DD, xln);
        mma_gemm<0, false, false><<<dim3(D3 / 128, BSr / 128), 256>>>(
            xln, wr + OFF_ATTN + (size_t)l * DD * D3, attn_b + (size_t)l * D3, nullptr,
            qkv, BSr, D3, DD);
        flash_kernel<<<dim3(SS / 64, BH), 128>>>(qkv, abuf);
        mma_gemm<2, false, false><<<dim3(DD / 128, BSr / 128), 256>>>(
            abuf, wr + OFF_PROJ + (size_t)l * DD * DD, proj_b + (size_t)l * DD, h,
            h, BSr, DD, DD);
        layernorm_kernel<<<BSr, 256>>>(h, ln2_g + l * DD, ln2_b + l * DD, xln);
        mma_gemm<1, false, false><<<dim3(D4 / 128, BSr / 128), 256>>>(
            xln, wr + OFF_FC + (size_t)l * DD * D4, fc_b + (size_t)l * D4, nullptr,
            fcb, BSr, D4, DD);
        mma_gemm<2, false, false><<<dim3(DD / 128, BSr / 128), 256>>>(
            fcb, wr + OFF_FC2 + (size_t)l * D4 * DD, fc2_b + (size_t)l * DD, h,
            h, BSr, DD, D4);
    }

    layernorm_kernel<<<BSr, 256>>>(h, lnf_g, lnf_b, xln);
    // Logits: NT, grid transposed (x = row tiles) so wte col-tiles hit L2 across row blocks
    mma_gemm<3, true, true><<<dim3(BSr / 128, (VV + 127) / 128), 256>>>(
        xln, wr + OFF_WTE, nullptr, nullptr, out, BSr, VV, DD);
}